// round 12
// baseline (speedup 1.0000x reference)
#include <cuda_runtime.h>
#include <math.h>

// Problem constants
#define NB   8
#define NT   2048
#define NJ   17
#define ND   129
#define NH   8
#define DH   16
#define NBJ  (NB * NJ)        // 136
#define NTOK (NBJ * NT)       // 278528
#define QKVN 384
#define TILE 128
#define PADA 132              // padded row stride for smem tiles (16B aligned)
#define KVSZ 272              // 16x16 kv + 16 ksum per (bj,h)

// Scratch (device globals: allocation-free rule)
__device__ float g_qkvm[(size_t)NTOK * QKVN];          // phi(q), phi(k), v per token
__device__ float g_kvtab[(size_t)NBJ * NH * KVSZ];     // per (bj,h): kv[16][16], ksum[16]

// ---------------- packed fp32x2 helpers (Blackwell FFMA2 path) ----------------
__device__ __forceinline__ unsigned long long pack_dup(float x) {
    unsigned long long r;
    asm("mov.b64 %0, {%1, %1};" : "=l"(r) : "f"(x));
    return r;
}
__device__ __forceinline__ void ffma2(unsigned long long& d, unsigned long long a,
                                      unsigned long long b) {
    asm("fma.rn.f32x2 %0, %1, %2, %0;" : "+l"(d) : "l"(a), "l"(b));
}
__device__ __forceinline__ float2 unpack2(unsigned long long v) {
    float2 f;
    asm("mov.b64 {%0, %1}, %2;" : "=f"(f.x), "=f"(f.y) : "l"(v));
    return f;
}

// Shared 128x128x128 micro-kernel: C[m0..+8][n0..+8] += As^T * Bs
// As, Bs are K-major: [k][m] / [k][n], row stride PADA.
__device__ __forceinline__ void gemm_tile_128(const float* __restrict__ As,
                                              const float* __restrict__ Bs,
                                              unsigned long long acc[8][4],
                                              int m0, int n0) {
#pragma unroll 4
    for (int k = 0; k < 128; k++) {
        const float4 a0 = *(const float4*)(As + k * PADA + m0);
        const float4 a1 = *(const float4*)(As + k * PADA + m0 + 4);
        const ulonglong2 b0 = *(const ulonglong2*)(Bs + k * PADA + n0);
        const ulonglong2 b1 = *(const ulonglong2*)(Bs + k * PADA + n0 + 4);
        unsigned long long bb[4] = {b0.x, b0.y, b1.x, b1.y};
        float av[8] = {a0.x, a0.y, a0.z, a0.w, a1.x, a1.y, a1.z, a1.w};
#pragma unroll
        for (int i = 0; i < 8; i++) {
            unsigned long long ad = pack_dup(av[i]);
#pragma unroll
            for (int u = 0; u < 4; u++) ffma2(acc[i][u], ad, bb[u]);
        }
    }
}

// ---------------------------------------------------------------------------
// Kernel 1: qkv = phi-epilogued GEMM.
// Grid: (NTOK/128, 3). blockIdx.y = s selects q/k/v 128-col slab of w_qkv.
// Each 128-token tile has a single (b, j) since 128 | T.
// ---------------------------------------------------------------------------
__global__ void __launch_bounds__(256, 1)
qkv_kernel(const float* __restrict__ x, const float* __restrict__ w_qkv,
           const float* __restrict__ b_qkv) {
    extern __shared__ float sm[];
    float* As = sm;                // [128][PADA]  x_spatial^T
    float* Bs = sm + TILE * PADA;  // [128][PADA]  w slab^T

    const int tile = blockIdx.x;
    const int s    = blockIdx.y;          // 0:q 1:k 2:v
    const int tid  = threadIdx.x;
    const int tok0 = tile * TILE;
    const int bj   = tok0 / NT;
    const int t0   = tok0 - bj * NT;
    const int b    = bj / NJ, j = bj - b * NJ;

    const float* xbase = x + ((size_t)(b * NT + t0) * NJ + j) * ND + 1;  // skip time col
    const size_t xstride = (size_t)NJ * ND;                               // 2193 floats

    const int lane = tid & 31;
    const int wp   = tid >> 5;
    // Load A tile (128 tokens x 128 spatial dims), transposed to K-major
    for (int r = wp; r < TILE; r += 8) {
        const float* xr = xbase + (size_t)r * xstride;
#pragma unroll
        for (int cc = 0; cc < 4; cc++) {
            int c = lane + 32 * cc;
            As[c * PADA + r] = __ldg(xr + c);
        }
    }
    // Load B slab (w_qkv rows s*128..s*128+127), transposed to K-major
    const float* wbase = w_qkv + (size_t)s * 128 * 128;
    for (int r = wp; r < 128; r += 8) {
        const float* wr = wbase + r * 128;
#pragma unroll
        for (int cc = 0; cc < 4; cc++) {
            int c = lane + 32 * cc;
            Bs[c * PADA + r] = __ldg(wr + c);
        }
    }
    __syncthreads();

    const int tm = tid >> 4, tn = tid & 15;
    const int m0 = tm * 8,  n0 = tn * 8;
    unsigned long long acc[8][4];
#pragma unroll
    for (int i = 0; i < 8; i++)
#pragma unroll
        for (int u = 0; u < 4; u++) acc[i][u] = 0ull;

    gemm_tile_128(As, Bs, acc, m0, n0);

    // Epilogue: +bias, phi (q,k slabs only), store to scratch
    float bias[8];
#pragma unroll
    for (int u = 0; u < 8; u++) bias[u] = __ldg(b_qkv + s * 128 + n0 + u);

#pragma unroll
    for (int i = 0; i < 8; i++) {
        float yv[8];
#pragma unroll
        for (int u = 0; u < 4; u++) {
            float2 p = unpack2(acc[i][u]);
            yv[2 * u]     = p.x + bias[2 * u];
            yv[2 * u + 1] = p.y + bias[2 * u + 1];
        }
        if (s < 2) {  // phi(x) = elu(x)+1
#pragma unroll
            for (int u = 0; u < 8; u++) {
                float v = yv[u];
                yv[u] = (v > 0.0f) ? (v + 1.0f) : expf(v);
            }
        }
        float* orow = g_qkvm + (size_t)(tok0 + m0 + i) * QKVN + s * 128 + n0;
        *(float4*)(orow)     = make_float4(yv[0], yv[1], yv[2], yv[3]);
        *(float4*)(orow + 4) = make_float4(yv[4], yv[5], yv[6], yv[7]);
    }
}

// ---------------------------------------------------------------------------
// Kernel 2: per (bj, h): kv[d][e] = sum_t k_m[t,d]*v[t,e], ksum[d] = sum_t k_m[t,d]
// Grid: NBJ*NH blocks, 256 threads; thread (i,e) owns kv[i][e].
// ---------------------------------------------------------------------------
__global__ void __launch_bounds__(256, 4)
kv_kernel() {
    const int bh = blockIdx.x;
    const int bj = bh >> 3, h = bh & 7;
    const int tid = threadIdx.x;
    const int i = tid >> 4, e = tid & 15;
    __shared__ float ks[16][16];
    __shared__ float vs[16][16];
    float kv = 0.0f, ksm = 0.0f;
    const size_t base = (size_t)bj * NT * QKVN + 128 + h * DH;  // k_m slab offset
    for (int tb = 0; tb < NT; tb += 16) {
#pragma unroll
        for (int r = 0; r < 2; r++) {
            int idx = tid + r * 256;
            int tt = idx >> 5;
            int which = (idx >> 4) & 1;  // 0 -> k_m, 1 -> v (offset +128)
            int li = idx & 15;
            float val = g_qkvm[base + (size_t)(tb + tt) * QKVN + which * 128 + li];
            if (which == 0) ks[tt][li] = val; else vs[tt][li] = val;
        }
        __syncthreads();
#pragma unroll
        for (int tt = 0; tt < 16; tt++) {
            float kk = ks[tt][i];
            kv = fmaf(kk, vs[tt][e], kv);
            if (e == 0) ksm += kk;
        }
        __syncthreads();
    }
    float* dst = g_kvtab + (size_t)bh * KVSZ;
    dst[i * 16 + e] = kv;
    if (e == 0) dst[256 + i] = ksm;
}

// ---------------------------------------------------------------------------
// Kernel 3: agg = (q_m @ kv) / clip(q_m . ksum, EPS), then y = agg @ w_out^T + b,
// y_time = sqrt(1 + |y|^2), write z = [y_time, y] at (B,T,J,D) layout.
// Grid: NTOK/128 blocks of 256 threads (one bj per block).
// ---------------------------------------------------------------------------
__global__ void __launch_bounds__(256, 1)
out_kernel(const float* __restrict__ w_out, const float* __restrict__ b_out,
           float* __restrict__ out) {
    extern __shared__ float sm[];
    float* Afs = sm;                     // [128][PADA] agg_flat^T (K-major)
    float* Ws  = sm + TILE * PADA;       // [128][PADA] w_out^T  (K-major)
    float* skv = sm + 2 * TILE * PADA;   // [NH*KVSZ]

    const int tile = blockIdx.x;
    const int tid  = threadIdx.x;
    const int tok0 = tile * TILE;
    const int bj   = tok0 / NT;
    const int t0   = tok0 - bj * NT;
    const int b    = bj / NJ, j = bj - b * NJ;

    const int lane = tid & 31, wp = tid >> 5;
    for (int r = wp; r < 128; r += 8) {
        const float* wr = w_out + r * 128;
#pragma unroll
        for (int cc = 0; cc < 4; cc++) {
            int c = lane + 32 * cc;
            Ws[c * PADA + r] = __ldg(wr + c);
        }
    }
    for (int idx = tid; idx < NH * KVSZ; idx += 256)
        skv[idx] = g_kvtab[(size_t)bj * NH * KVSZ + idx];
    __syncthreads();

    // Phase 1: agg_flat for 128 tokens (2 threads/token, 4 heads each)
    {
        const int m  = tid >> 1;
        const int hb = (tid & 1) * 4;
        const float* qrow = g_qkvm + (size_t)(tok0 + m) * QKVN;  // q_m at slab 0
#pragma unroll
        for (int hh = 0; hh < 4; hh++) {
            const int h = hb + hh;
            float q[16];
            const float4* q4 = (const float4*)(qrow + h * DH);
#pragma unroll
            for (int u = 0; u < 4; u++) {
                float4 t = q4[u];
                q[4 * u] = t.x; q[4 * u + 1] = t.y; q[4 * u + 2] = t.z; q[4 * u + 3] = t.w;
            }
            const float* kvh = skv + h * KVSZ;
            float a[16];
#pragma unroll
            for (int e = 0; e < 16; e++) a[e] = 0.0f;
            float denom = 0.0f;
#pragma unroll
            for (int i = 0; i < 16; i++) {
                const float qi = q[i];
                const float4* kr = (const float4*)(kvh + i * 16);
#pragma unroll
                for (int u = 0; u < 4; u++) {
                    float4 t = kr[u];
                    a[4 * u]     = fmaf(qi, t.x, a[4 * u]);
                    a[4 * u + 1] = fmaf(qi, t.y, a[4 * u + 1]);
                    a[4 * u + 2] = fmaf(qi, t.z, a[4 * u + 2]);
                    a[4 * u + 3] = fmaf(qi, t.w, a[4 * u + 3]);
                }
                denom = fmaf(qi, kvh[256 + i], denom);
            }
            denom = fmaxf(denom, 1e-6f);
            const float inv = 1.0f / denom;
#pragma unroll
            for (int e = 0; e < 16; e++)
                Afs[(h * DH + e) * PADA + m] = a[e] * inv;
        }
    }
    __syncthreads();

    // Phase 2: y = agg_flat @ w_out^T
    const int tm = tid >> 4, tn = tid & 15;
    const int m0 = tm * 8,  n0 = tn * 8;
    unsigned long long acc[8][4];
#pragma unroll
    for (int i = 0; i < 8; i++)
#pragma unroll
        for (int u = 0; u < 4; u++) acc[i][u] = 0ull;

    gemm_tile_128(Afs, Ws, acc, m0, n0);

    float bias[8];
#pragma unroll
    for (int u = 0; u < 8; u++) bias[u] = __ldg(b_out + n0 + u);

    // Epilogue: bias, per-token |y|^2 via half-warp shfl (16 threads own a row),
    // y_time, scatter to (B,T,J,129) layout.
#pragma unroll
    for (int i = 0; i < 8; i++) {
        float yv[8];
#pragma unroll
        for (int u = 0; u < 4; u++) {
            float2 p = unpack2(acc[i][u]);
            yv[2 * u]     = p.x + bias[2 * u];
            yv[2 * u + 1] = p.y + bias[2 * u + 1];
        }
        float p = 0.0f;
#pragma unroll
        for (int u = 0; u < 8; u++) p = fmaf(yv[u], yv[u], p);
        p += __shfl_xor_sync(0xffffffffu, p, 1);
        p += __shfl_xor_sync(0xffffffffu, p, 2);
        p += __shfl_xor_sync(0xffffffffu, p, 4);
        p += __shfl_xor_sync(0xffffffffu, p, 8);

        const int t = t0 + m0 + i;
        float* orow = out + ((size_t)(b * NT + t) * NJ + j) * ND;
        if (tn == 0) orow[0] = sqrtf(1.0f + p);
#pragma unroll
        for (int u = 0; u < 8; u++) orow[1 + n0 + u] = yv[u];
    }
}

// ---------------------------------------------------------------------------
extern "C" void kernel_launch(void* const* d_in, const int* in_sizes, int n_in,
                              void* d_out, int out_size) {
    (void)in_sizes; (void)n_in; (void)out_size;
    const float* x     = (const float*)d_in[0];
    const float* w_qkv = (const float*)d_in[1];
    const float* b_qkv = (const float*)d_in[2];
    const float* w_out = (const float*)d_in[3];
    const float* b_out = (const float*)d_in[4];
    float* out = (float*)d_out;

    const int smem1 = 2 * TILE * PADA * 4;                    // 135168 B
    const int smem3 = (2 * TILE * PADA + NH * KVSZ) * 4;      // 143872 B
    cudaFuncSetAttribute(qkv_kernel, cudaFuncAttributeMaxDynamicSharedMemorySize, smem1);
    cudaFuncSetAttribute(out_kernel, cudaFuncAttributeMaxDynamicSharedMemorySize, smem3);

    qkv_kernel<<<dim3(NTOK / TILE, 3), 256, smem1>>>(x, w_qkv, b_qkv);
    kv_kernel<<<NBJ * NH, 256>>>();
    out_kernel<<<NTOK / TILE, 256, smem3>>>(w_out, b_out, out);
}

// round 13
// speedup vs baseline: 1.0014x; 1.0014x over previous
#include <cuda_runtime.h>
#include <math.h>

// Problem constants
#define NB   8
#define NT   2048
#define NJ   17
#define ND   129
#define NH   8
#define DH   16
#define NBJ  (NB * NJ)        // 136
#define NTOK (NBJ * NT)       // 278528
#define QKVN 384
#define TILE 128
#define PADA 132              // padded row stride for smem tiles (16B aligned)
#define KVSZ 272              // 16x16 kv + 16 ksum per (bj,h)

// Scratch (device globals: allocation-free rule)
__device__ float g_qkvm[(size_t)NTOK * QKVN];          // phi(q), phi(k), v per token
__device__ float g_kvtab[(size_t)NBJ * NH * KVSZ];     // per (bj,h): kv[16][16], ksum[16]

// ---------------- packed fp32x2 helpers (Blackwell FFMA2 path) ----------------
__device__ __forceinline__ unsigned long long pack_dup(float x) {
    unsigned long long r;
    asm("mov.b64 %0, {%1, %1};" : "=l"(r) : "f"(x));
    return r;
}
__device__ __forceinline__ void ffma2(unsigned long long& d, unsigned long long a,
                                      unsigned long long b) {
    asm("fma.rn.f32x2 %0, %1, %2, %0;" : "+l"(d) : "l"(a), "l"(b));
}
__device__ __forceinline__ float2 unpack2(unsigned long long v) {
    float2 f;
    asm("mov.b64 {%0, %1}, %2;" : "=f"(f.x), "=f"(f.y) : "l"(v));
    return f;
}

// Shared 128x128x128 micro-kernel: C[m0..+8][n0..+8] += As^T * Bs
// As, Bs are K-major: [k][m] / [k][n], row stride PADA.
__device__ __forceinline__ void gemm_tile_128(const float* __restrict__ As,
                                              const float* __restrict__ Bs,
                                              unsigned long long acc[8][4],
                                              int m0, int n0) {
#pragma unroll 4
    for (int k = 0; k < 128; k++) {
        const float4 a0 = *(const float4*)(As + k * PADA + m0);
        const float4 a1 = *(const float4*)(As + k * PADA + m0 + 4);
        const ulonglong2 b0 = *(const ulonglong2*)(Bs + k * PADA + n0);
        const ulonglong2 b1 = *(const ulonglong2*)(Bs + k * PADA + n0 + 4);
        unsigned long long bb[4] = {b0.x, b0.y, b1.x, b1.y};
        float av[8] = {a0.x, a0.y, a0.z, a0.w, a1.x, a1.y, a1.z, a1.w};
#pragma unroll
        for (int i = 0; i < 8; i++) {
            unsigned long long ad = pack_dup(av[i]);
#pragma unroll
            for (int u = 0; u < 4; u++) ffma2(acc[i][u], ad, bb[u]);
        }
    }
}

// ---------------------------------------------------------------------------
// Kernel 1: qkv = phi-epilogued GEMM.
// Grid: (NTOK/128, 3). blockIdx.y = s selects q/k/v 128-col slab of w_qkv.
// Each 128-token tile has a single (b, j) since 128 | T.
// ---------------------------------------------------------------------------
__global__ void __launch_bounds__(256, 1)
qkv_kernel(const float* __restrict__ x, const float* __restrict__ w_qkv,
           const float* __restrict__ b_qkv) {
    extern __shared__ float sm[];
    float* As = sm;                // [128][PADA]  x_spatial^T
    float* Bs = sm + TILE * PADA;  // [128][PADA]  w slab^T

    const int tile = blockIdx.x;
    const int s    = blockIdx.y;          // 0:q 1:k 2:v
    const int tid  = threadIdx.x;
    const int tok0 = tile * TILE;
    const int bj   = tok0 / NT;
    const int t0   = tok0 - bj * NT;
    const int b    = bj / NJ, j = bj - b * NJ;

    const float* xbase = x + ((size_t)(b * NT + t0) * NJ + j) * ND + 1;  // skip time col
    const size_t xstride = (size_t)NJ * ND;                               // 2193 floats

    const int lane = tid & 31;
    const int wp   = tid >> 5;
    // Load A tile (128 tokens x 128 spatial dims), transposed to K-major
    for (int r = wp; r < TILE; r += 8) {
        const float* xr = xbase + (size_t)r * xstride;
#pragma unroll
        for (int cc = 0; cc < 4; cc++) {
            int c = lane + 32 * cc;
            As[c * PADA + r] = __ldg(xr + c);
        }
    }
    // Load B slab (w_qkv rows s*128..s*128+127), transposed to K-major
    const float* wbase = w_qkv + (size_t)s * 128 * 128;
    for (int r = wp; r < 128; r += 8) {
        const float* wr = wbase + r * 128;
#pragma unroll
        for (int cc = 0; cc < 4; cc++) {
            int c = lane + 32 * cc;
            Bs[c * PADA + r] = __ldg(wr + c);
        }
    }
    __syncthreads();

    const int tm = tid >> 4, tn = tid & 15;
    const int m0 = tm * 8,  n0 = tn * 8;
    unsigned long long acc[8][4];
#pragma unroll
    for (int i = 0; i < 8; i++)
#pragma unroll
        for (int u = 0; u < 4; u++) acc[i][u] = 0ull;

    gemm_tile_128(As, Bs, acc, m0, n0);

    // Epilogue: +bias, phi (q,k slabs only), store to scratch
    float bias[8];
#pragma unroll
    for (int u = 0; u < 8; u++) bias[u] = __ldg(b_qkv + s * 128 + n0 + u);

#pragma unroll
    for (int i = 0; i < 8; i++) {
        float yv[8];
#pragma unroll
        for (int u = 0; u < 4; u++) {
            float2 p = unpack2(acc[i][u]);
            yv[2 * u]     = p.x + bias[2 * u];
            yv[2 * u + 1] = p.y + bias[2 * u + 1];
        }
        if (s < 2) {  // phi(x) = elu(x)+1
#pragma unroll
            for (int u = 0; u < 8; u++) {
                float v = yv[u];
                yv[u] = (v > 0.0f) ? (v + 1.0f) : expf(v);
            }
        }
        float* orow = g_qkvm + (size_t)(tok0 + m0 + i) * QKVN + s * 128 + n0;
        *(float4*)(orow)     = make_float4(yv[0], yv[1], yv[2], yv[3]);
        *(float4*)(orow + 4) = make_float4(yv[4], yv[5], yv[6], yv[7]);
    }
}

// ---------------------------------------------------------------------------
// Kernel 2: per (bj, h): kv[d][e] = sum_t k_m[t,d]*v[t,e], ksum[d] = sum_t k_m[t,d]
// Grid: NBJ*NH blocks, 256 threads; thread (i,e) owns kv[i][e].
// ---------------------------------------------------------------------------
__global__ void __launch_bounds__(256, 4)
kv_kernel() {
    const int bh = blockIdx.x;
    const int bj = bh >> 3, h = bh & 7;
    const int tid = threadIdx.x;
    const int i = tid >> 4, e = tid & 15;
    __shared__ float ks[16][16];
    __shared__ float vs[16][16];
    float kv = 0.0f, ksm = 0.0f;
    const size_t base = (size_t)bj * NT * QKVN + 128 + h * DH;  // k_m slab offset
    for (int tb = 0; tb < NT; tb += 16) {
#pragma unroll
        for (int r = 0; r < 2; r++) {
            int idx = tid + r * 256;
            int tt = idx >> 5;
            int which = (idx >> 4) & 1;  // 0 -> k_m, 1 -> v (offset +128)
            int li = idx & 15;
            float val = g_qkvm[base + (size_t)(tb + tt) * QKVN + which * 128 + li];
            if (which == 0) ks[tt][li] = val; else vs[tt][li] = val;
        }
        __syncthreads();
#pragma unroll
        for (int tt = 0; tt < 16; tt++) {
            float kk = ks[tt][i];
            kv = fmaf(kk, vs[tt][e], kv);
            if (e == 0) ksm += kk;
        }
        __syncthreads();
    }
    float* dst = g_kvtab + (size_t)bh * KVSZ;
    dst[i * 16 + e] = kv;
    if (e == 0) dst[256 + i] = ksm;
}

// ---------------------------------------------------------------------------
// Kernel 3: agg = (q_m @ kv) / clip(q_m . ksum, EPS), then y = agg @ w_out^T + b,
// y_time = sqrt(1 + |y|^2), write z = [y_time, y] at (B,T,J,D) layout.
// Grid: NTOK/128 blocks of 256 threads (one bj per block).
// ---------------------------------------------------------------------------
__global__ void __launch_bounds__(256, 1)
out_kernel(const float* __restrict__ w_out, const float* __restrict__ b_out,
           float* __restrict__ out) {
    extern __shared__ float sm[];
    float* Afs = sm;                     // [128][PADA] agg_flat^T (K-major)
    float* Ws  = sm + TILE * PADA;       // [128][PADA] w_out^T  (K-major)
    float* skv = sm + 2 * TILE * PADA;   // [NH*KVSZ]

    const int tile = blockIdx.x;
    const int tid  = threadIdx.x;
    const int tok0 = tile * TILE;
    const int bj   = tok0 / NT;
    const int t0   = tok0 - bj * NT;
    const int b    = bj / NJ, j = bj - b * NJ;

    const int lane = tid & 31, wp = tid >> 5;
    for (int r = wp; r < 128; r += 8) {
        const float* wr = w_out + r * 128;
#pragma unroll
        for (int cc = 0; cc < 4; cc++) {
            int c = lane + 32 * cc;
            Ws[c * PADA + r] = __ldg(wr + c);
        }
    }
    for (int idx = tid; idx < NH * KVSZ; idx += 256)
        skv[idx] = g_kvtab[(size_t)bj * NH * KVSZ + idx];
    __syncthreads();

    // Phase 1: agg_flat for 128 tokens (2 threads/token, 4 heads each)
    {
        const int m  = tid >> 1;
        const int hb = (tid & 1) * 4;
        const float* qrow = g_qkvm + (size_t)(tok0 + m) * QKVN;  // q_m at slab 0
#pragma unroll
        for (int hh = 0; hh < 4; hh++) {
            const int h = hb + hh;
            float q[16];
            const float4* q4 = (const float4*)(qrow + h * DH);
#pragma unroll
            for (int u = 0; u < 4; u++) {
                float4 t = q4[u];
                q[4 * u] = t.x; q[4 * u + 1] = t.y; q[4 * u + 2] = t.z; q[4 * u + 3] = t.w;
            }
            const float* kvh = skv + h * KVSZ;
            float a[16];
#pragma unroll
            for (int e = 0; e < 16; e++) a[e] = 0.0f;
            float denom = 0.0f;
#pragma unroll
            for (int i = 0; i < 16; i++) {
                const float qi = q[i];
                const float4* kr = (const float4*)(kvh + i * 16);
#pragma unroll
                for (int u = 0; u < 4; u++) {
                    float4 t = kr[u];
                    a[4 * u]     = fmaf(qi, t.x, a[4 * u]);
                    a[4 * u + 1] = fmaf(qi, t.y, a[4 * u + 1]);
                    a[4 * u + 2] = fmaf(qi, t.z, a[4 * u + 2]);
                    a[4 * u + 3] = fmaf(qi, t.w, a[4 * u + 3]);
                }
                denom = fmaf(qi, kvh[256 + i], denom);
            }
            denom = fmaxf(denom, 1e-6f);
            const float inv = 1.0f / denom;
#pragma unroll
            for (int e = 0; e < 16; e++)
                Afs[(h * DH + e) * PADA + m] = a[e] * inv;
        }
    }
    __syncthreads();

    // Phase 2: y = agg_flat @ w_out^T
    const int tm = tid >> 4, tn = tid & 15;
    const int m0 = tm * 8,  n0 = tn * 8;
    unsigned long long acc[8][4];
#pragma unroll
    for (int i = 0; i < 8; i++)
#pragma unroll
        for (int u = 0; u < 4; u++) acc[i][u] = 0ull;

    gemm_tile_128(Afs, Ws, acc, m0, n0);

    float bias[8];
#pragma unroll
    for (int u = 0; u < 8; u++) bias[u] = __ldg(b_out + n0 + u);

    // Epilogue: bias, per-token |y|^2 via half-warp shfl (16 threads own a row),
    // y_time, scatter to (B,T,J,129) layout.
#pragma unroll
    for (int i = 0; i < 8; i++) {
        float yv[8];
#pragma unroll
        for (int u = 0; u < 4; u++) {
            float2 p = unpack2(acc[i][u]);
            yv[2 * u]     = p.x + bias[2 * u];
            yv[2 * u + 1] = p.y + bias[2 * u + 1];
        }
        float p = 0.0f;
#pragma unroll
        for (int u = 0; u < 8; u++) p = fmaf(yv[u], yv[u], p);
        p += __shfl_xor_sync(0xffffffffu, p, 1);
        p += __shfl_xor_sync(0xffffffffu, p, 2);
        p += __shfl_xor_sync(0xffffffffu, p, 4);
        p += __shfl_xor_sync(0xffffffffu, p, 8);

        const int t = t0 + m0 + i;
        float* orow = out + ((size_t)(b * NT + t) * NJ + j) * ND;
        if (tn == 0) orow[0] = sqrtf(1.0f + p);
#pragma unroll
        for (int u = 0; u < 8; u++) orow[1 + n0 + u] = yv[u];
    }
}

// ---------------------------------------------------------------------------
extern "C" void kernel_launch(void* const* d_in, const int* in_sizes, int n_in,
                              void* d_out, int out_size) {
    (void)in_sizes; (void)n_in; (void)out_size;
    const float* x     = (const float*)d_in[0];
    const float* w_qkv = (const float*)d_in[1];
    const float* b_qkv = (const float*)d_in[2];
    const float* w_out = (const float*)d_in[3];
    const float* b_out = (const float*)d_in[4];
    float* out = (float*)d_out;

    const int smem1 = 2 * TILE * PADA * 4;                    // 135168 B
    const int smem3 = (2 * TILE * PADA + NH * KVSZ) * 4;      // 143872 B
    cudaFuncSetAttribute(qkv_kernel, cudaFuncAttributeMaxDynamicSharedMemorySize, smem1);
    cudaFuncSetAttribute(out_kernel, cudaFuncAttributeMaxDynamicSharedMemorySize, smem3);

    qkv_kernel<<<dim3(NTOK / TILE, 3), 256, smem1>>>(x, w_qkv, b_qkv);
    kv_kernel<<<NBJ * NH, 256>>>();
    out_kernel<<<NTOK / TILE, 256, smem3>>>(w_out, b_out, out);
}

// round 15
// speedup vs baseline: 1.5473x; 1.5451x over previous
#include <cuda_runtime.h>
#include <cuda_bf16.h>
#include <math.h>
#include <stdint.h>

// Problem constants
#define NB   8
#define NT   2048
#define NJ   17
#define ND   129
#define NH   8
#define DH   16
#define NBJ  (NB * NJ)        // 136
#define NTOK (NBJ * NT)       // 278528
#define QKVN 384
#define KVSZ 272              // 16x16 kv + 16 ksum per (bj,h)

// Scratch (device globals: allocation-free rule)
__device__ float g_qkvm[(size_t)NTOK * QKVN];          // phi(q), phi(k), v per token
__device__ float g_kvtab[(size_t)NBJ * NH * KVSZ];     // per (bj,h): kv[16][16], ksum[16]

// ---------------- smem layout (dynamic) ----------------
// bf16 128x128 tiles, row stride 272B (136 bf16): ldmatrix conflict-free
// (272 mod 128 = 16 -> 8 rows hit 8 distinct 16B banks).
#define RSB      272
#define OFF_AHI  0
#define OFF_ALO  (128 * RSB)       // 34816
#define OFF_BHI  (2 * 128 * RSB)   // 69632
#define OFF_BLO  (3 * 128 * RSB)   // 104448
#define SMEM_K1  (4 * 128 * RSB)   // 139264
#define OFF_KV   SMEM_K1
#define SMEM_K3  (SMEM_K1 + NH * KVSZ * 4)  // 147968
#define CPAD     132               // fp32 staging row stride (floats), K3 only

// ---------------------------- PTX helpers ----------------------------------
__device__ __forceinline__ uint32_t smem_u32(const void* p) {
    uint32_t a;
    asm("{ .reg .u64 t; cvta.to.shared.u64 t, %1; cvt.u32.u64 %0, t; }" : "=r"(a) : "l"(p));
    return a;
}

#define LDSM_X4(r0, r1, r2, r3, addr) \
    asm volatile("ldmatrix.sync.aligned.m8n8.x4.shared.b16 {%0,%1,%2,%3}, [%4];" \
                 : "=r"(r0), "=r"(r1), "=r"(r2), "=r"(r3) : "r"(addr))

#define MMA16816(d, a, b) \
    asm volatile("mma.sync.aligned.m16n8k16.row.col.f32.bf16.bf16.f32 " \
                 "{%0,%1,%2,%3}, {%4,%5,%6,%7}, {%8,%9}, {%0,%1,%2,%3};" \
                 : "+f"((d)[0]), "+f"((d)[1]), "+f"((d)[2]), "+f"((d)[3]) \
                 : "r"((a)[0]), "r"((a)[1]), "r"((a)[2]), "r"((a)[3]), \
                   "r"((b)[0]), "r"((b)[1]))

__device__ __forceinline__ void cvt_hilo(float v, __nv_bfloat16& h, __nv_bfloat16& l) {
    h = __float2bfloat16(v);
    l = __float2bfloat16(v - __bfloat162float(h));
}

// Convert a 128x128 fp32 row-major matrix (8B-aligned rows, stride 128) into
// the hi/lo bf16 tiles at OFF_BHI / OFF_BLO.
__device__ __forceinline__ void conv_w(char* smc, const float* __restrict__ w,
                                       int wid, int nw, int lane) {
    for (int r = wid; r < 128; r += nw) {
        const float* wr = w + r * 128;
#pragma unroll
        for (int cb = 0; cb < 128; cb += 64) {
            int c = cb + 2 * lane;
            float2 v = __ldg((const float2*)(wr + c));
            __nv_bfloat16 h0, l0, h1, l1;
            cvt_hilo(v.x, h0, l0);
            cvt_hilo(v.y, h1, l1);
            uint32_t off = (uint32_t)r * RSB + (uint32_t)c * 2;
            __nv_bfloat162 hp; hp.x = h0; hp.y = h1;
            __nv_bfloat162 lp; lp.x = l0; lp.y = l1;
            *(__nv_bfloat162*)(smc + OFF_BHI + off) = hp;
            *(__nv_bfloat162*)(smc + OFF_BLO + off) = lp;
        }
    }
}

// 3-term bf16-split 128x128x128 GEMM into acc[2][8][4].
// Warp tile: M=32 (2 m16), N=64 (8 n8). aA_*/aB_* are per-lane ldmatrix bases.
__device__ __forceinline__ void mma_split_128(uint32_t aA_hi, uint32_t aA_lo,
                                              uint32_t aB_hi, uint32_t aB_lo,
                                              float acc[2][8][4]) {
    for (int term = 0; term < 3; term++) {
        const uint32_t aA = (term == 1) ? aA_lo : aA_hi;
        const uint32_t aB = (term == 2) ? aB_lo : aB_hi;
#pragma unroll 2
        for (int ks = 0; ks < 8; ks++) {
            const uint32_t ko = (uint32_t)ks * 32;
            uint32_t af[2][4];
#pragma unroll
            for (int mi = 0; mi < 2; mi++)
                LDSM_X4(af[mi][0], af[mi][1], af[mi][2], af[mi][3],
                        aA + (uint32_t)mi * (16 * RSB) + ko);
            uint32_t bf[8][2];
#pragma unroll
            for (int nb = 0; nb < 4; nb++) {
                uint32_t t0, t1, t2, t3;
                LDSM_X4(t0, t1, t2, t3, aB + (uint32_t)nb * (16 * RSB) + ko);
                bf[2 * nb][0] = t0; bf[2 * nb][1] = t1;
                bf[2 * nb + 1][0] = t2; bf[2 * nb + 1][1] = t3;
            }
#pragma unroll
            for (int mi = 0; mi < 2; mi++)
#pragma unroll
                for (int nt = 0; nt < 8; nt++)
                    MMA16816(acc[mi][nt], af[mi], bf[nt]);
        }
    }
}

// ---------------------------------------------------------------------------
// Kernel 1: qkv GEMM via HMMA. One CTA = 128 tokens x all 3 slabs (q,k,v).
// ---------------------------------------------------------------------------
__global__ void __launch_bounds__(256, 1)
qkv_kernel(const float* __restrict__ x, const float* __restrict__ w_qkv,
           const float* __restrict__ b_qkv) {
    extern __shared__ char smc[];
    const uint32_t sb = smem_u32(smc);
    const int tid = threadIdx.x, lane = tid & 31, wp = tid >> 5;

    const int tok0 = blockIdx.x * 128;
    const int bj = tok0 / NT;
    const int t0 = tok0 - bj * NT;
    const int b = bj / NJ, j = bj - b * NJ;
    const float* xbase = x + ((size_t)(b * NT + t0) * NJ + j) * ND + 1;  // skip time col
    const size_t xstride = (size_t)NJ * ND;

    // A tile: 128 tokens x 128 dims -> hi/lo bf16 (x rows 4B-aligned: scalar ld)
    for (int r = wp; r < 128; r += 8) {
        const float* xr = xbase + (size_t)r * xstride;
#pragma unroll
        for (int cb = 0; cb < 128; cb += 64) {
            int c = cb + 2 * lane;
            float v0 = __ldg(xr + c), v1 = __ldg(xr + c + 1);
            __nv_bfloat16 h0, l0, h1, l1;
            cvt_hilo(v0, h0, l0);
            cvt_hilo(v1, h1, l1);
            uint32_t off = (uint32_t)r * RSB + (uint32_t)c * 2;
            __nv_bfloat162 hp; hp.x = h0; hp.y = h1;
            __nv_bfloat162 lp; lp.x = l0; lp.y = l1;
            *(__nv_bfloat162*)(smc + OFF_AHI + off) = hp;
            *(__nv_bfloat162*)(smc + OFF_ALO + off) = lp;
        }
    }

    // Warp tiling + per-lane ldmatrix offsets
    const int wm = wp & 3, wn = wp >> 2;
    const int m0 = wm * 32, n0 = wn * 64;
    const uint32_t a_loff = (uint32_t)(lane & 7) * RSB + (uint32_t)((lane >> 3) & 1) * (8 * RSB)
                          + (uint32_t)(lane >> 4) * 16;
    const uint32_t b_loff = (uint32_t)(lane & 7) * RSB + (uint32_t)((lane >> 3) & 1) * 16
                          + (uint32_t)(lane >> 4) * (8 * RSB);
    const uint32_t aA_hi = sb + OFF_AHI + (uint32_t)m0 * RSB + a_loff;
    const uint32_t aA_lo = sb + OFF_ALO + (uint32_t)m0 * RSB + a_loff;
    const uint32_t aB_hi = sb + OFF_BHI + (uint32_t)n0 * RSB + b_loff;
    const uint32_t aB_lo = sb + OFF_BLO + (uint32_t)n0 * RSB + b_loff;

    for (int s = 0; s < 3; s++) {
        if (s > 0) __syncthreads();  // epilogue(s-1) done before overwriting B
        conv_w(smc, w_qkv + (size_t)s * 128 * 128, wp, 8, lane);
        __syncthreads();

        float acc[2][8][4];
#pragma unroll
        for (int mi = 0; mi < 2; mi++)
#pragma unroll
            for (int nt = 0; nt < 8; nt++)
#pragma unroll
                for (int u = 0; u < 4; u++) acc[mi][nt][u] = 0.0f;

        mma_split_128(aA_hi, aA_lo, aB_hi, aB_lo, acc);

        // Fragment-direct epilogue: +bias, phi for q/k slabs, store to scratch.
        float2 bv[8];
#pragma unroll
        for (int nt = 0; nt < 8; nt++)
            bv[nt] = __ldg((const float2*)(b_qkv + s * 128 + n0 + nt * 8 + 2 * (lane & 3)));

#pragma unroll
        for (int mi = 0; mi < 2; mi++) {
            const int r0 = m0 + mi * 16 + (lane >> 2);
            float* row0 = g_qkvm + (size_t)(tok0 + r0) * QKVN + s * 128 + n0 + 2 * (lane & 3);
            float* row1 = row0 + 8 * QKVN;
#pragma unroll
            for (int nt = 0; nt < 8; nt++) {
                float y00 = acc[mi][nt][0] + bv[nt].x;
                float y01 = acc[mi][nt][1] + bv[nt].y;
                float y10 = acc[mi][nt][2] + bv[nt].x;
                float y11 = acc[mi][nt][3] + bv[nt].y;
                if (s < 2) {  // phi = elu + 1
                    y00 = (y00 > 0.0f) ? (y00 + 1.0f) : expf(y00);
                    y01 = (y01 > 0.0f) ? (y01 + 1.0f) : expf(y01);
                    y10 = (y10 > 0.0f) ? (y10 + 1.0f) : expf(y10);
                    y11 = (y11 > 0.0f) ? (y11 + 1.0f) : expf(y11);
                }
                *(float2*)(row0 + nt * 8) = make_float2(y00, y01);
                *(float2*)(row1 + nt * 8) = make_float2(y10, y11);
            }
        }
    }
}

// ---------------------------------------------------------------------------
// Kernel 2: per (bj, h): kv[d][e] = sum_t k_m[t,d]*v[t,e], ksum[d] = sum_t k_m[t,d]
// ---------------------------------------------------------------------------
__global__ void __launch_bounds__(256, 4)
kv_kernel() {
    const int bh = blockIdx.x;
    const int bj = bh >> 3, h = bh & 7;
    const int tid = threadIdx.x;
    const int i = tid >> 4, e = tid & 15;
    __shared__ float ks[16][16];
    __shared__ float vs[16][16];
    float kv = 0.0f, ksm = 0.0f;
    const size_t base = (size_t)bj * NT * QKVN + 128 + h * DH;  // k_m slab offset
    for (int tb = 0; tb < NT; tb += 16) {
#pragma unroll
        for (int r = 0; r < 2; r++) {
            int idx = tid + r * 256;
            int tt = idx >> 5;
            int which = (idx >> 4) & 1;  // 0 -> k_m, 1 -> v (offset +128)
            int li = idx & 15;
            float val = g_qkvm[base + (size_t)(tb + tt) * QKVN + which * 128 + li];
            if (which == 0) ks[tt][li] = val; else vs[tt][li] = val;
        }
        __syncthreads();
#pragma unroll
        for (int tt = 0; tt < 16; tt++) {
            float kk = ks[tt][i];
            kv = fmaf(kk, vs[tt][e], kv);
            if (e == 0) ksm += kk;
        }
        __syncthreads();
    }
    float* dst = g_kvtab + (size_t)bh * KVSZ;
    dst[i * 16 + e] = kv;
    if (e == 0) dst[256 + i] = ksm;
}

// ---------------------------------------------------------------------------
// Kernel 3: agg = (q_m @ kv) / clip(q_m . ksum, EPS) -> bf16 hi/lo A tile,
// y = agg @ w_out^T + b via HMMA, y_time epilogue via smem staging.
// ---------------------------------------------------------------------------
__global__ void __launch_bounds__(256, 1)
out_kernel(const float* __restrict__ w_out, const float* __restrict__ b_out,
           float* __restrict__ out) {
    extern __shared__ char smc[];
    const uint32_t sb = smem_u32(smc);
    float* skv = (float*)(smc + OFF_KV);
    const int tid = threadIdx.x, lane = tid & 31, wp = tid >> 5;

    const int tok0 = blockIdx.x * 128;
    const int bj = tok0 / NT;
    const int t0 = tok0 - bj * NT;
    const int b = bj / NJ, j = bj - b * NJ;

    conv_w(smc, w_out, wp, 8, lane);
    for (int idx = tid; idx < NH * KVSZ; idx += 256)
        skv[idx] = g_kvtab[(size_t)bj * NH * KVSZ + idx];
    __syncthreads();

    // Phase 1: agg_flat for 128 tokens (2 threads/token, 4 heads each),
    // written as bf16 hi/lo directly into the A tile.
    {
        const int m  = tid >> 1;
        const int hb = (tid & 1) * 4;
        const float* qrow = g_qkvm + (size_t)(tok0 + m) * QKVN;  // q_m at slab 0
#pragma unroll
        for (int hh = 0; hh < 4; hh++) {
            const int h = hb + hh;
            float q[16];
            const float4* q4 = (const float4*)(qrow + h * DH);
#pragma unroll
            for (int u = 0; u < 4; u++) {
                float4 t = q4[u];
                q[4 * u] = t.x; q[4 * u + 1] = t.y; q[4 * u + 2] = t.z; q[4 * u + 3] = t.w;
            }
            const float* kvh = skv + h * KVSZ;
            float a[16];
#pragma unroll
            for (int e2 = 0; e2 < 16; e2++) a[e2] = 0.0f;
            float denom = 0.0f;
#pragma unroll
            for (int i = 0; i < 16; i++) {
                const float qi = q[i];
                const float4* kr = (const float4*)(kvh + i * 16);
#pragma unroll
                for (int u = 0; u < 4; u++) {
                    float4 t = kr[u];
                    a[4 * u]     = fmaf(qi, t.x, a[4 * u]);
                    a[4 * u + 1] = fmaf(qi, t.y, a[4 * u + 1]);
                    a[4 * u + 2] = fmaf(qi, t.z, a[4 * u + 2]);
                    a[4 * u + 3] = fmaf(qi, t.w, a[4 * u + 3]);
                }
                denom = fmaf(qi, kvh[256 + i], denom);
            }
            denom = fmaxf(denom, 1e-6f);
            const float inv = 1.0f / denom;
#pragma unroll
            for (int e2 = 0; e2 < 16; e2 += 2) {
                __nv_bfloat16 h0, l0, h1, l1;
                cvt_hilo(a[e2] * inv, h0, l0);
                cvt_hilo(a[e2 + 1] * inv, h1, l1);
                uint32_t off = (uint32_t)m * RSB + (uint32_t)(h * DH + e2) * 2;
                __nv_bfloat162 hp; hp.x = h0; hp.y = h1;
                __nv_bfloat162 lp; lp.x = l0; lp.y = l1;
                *(__nv_bfloat162*)(smc + OFF_AHI + off) = hp;
                *(__nv_bfloat162*)(smc + OFF_ALO + off) = lp;
            }
        }
    }
    __syncthreads();

    const int wm = wp & 3, wn = wp >> 2;
    const int m0 = wm * 32, n0 = wn * 64;
    const uint32_t a_loff = (uint32_t)(lane & 7) * RSB + (uint32_t)((lane >> 3) & 1) * (8 * RSB)
                          + (uint32_t)(lane >> 4) * 16;
    const uint32_t b_loff = (uint32_t)(lane & 7) * RSB + (uint32_t)((lane >> 3) & 1) * 16
                          + (uint32_t)(lane >> 4) * (8 * RSB);
    const uint32_t aA_hi = sb + OFF_AHI + (uint32_t)m0 * RSB + a_loff;
    const uint32_t aA_lo = sb + OFF_ALO + (uint32_t)m0 * RSB + a_loff;
    const uint32_t aB_hi = sb + OFF_BHI + (uint32_t)n0 * RSB + b_loff;
    const uint32_t aB_lo = sb + OFF_BLO + (uint32_t)n0 * RSB + b_loff;

    float acc[2][8][4];
#pragma unroll
    for (int mi = 0; mi < 2; mi++)
#pragma unroll
        for (int nt = 0; nt < 8; nt++)
#pragma unroll
            for (int u = 0; u < 4; u++) acc[mi][nt][u] = 0.0f;

    mma_split_128(aA_hi, aA_lo, aB_hi, aB_lo, acc);
    __syncthreads();  // all warps done reading B before staging overwrites it

    // Stage y (pre-bias) to fp32 smem over the B region
    float* Csm = (float*)(smc + OFF_BHI);
#pragma unroll
    for (int mi = 0; mi < 2; mi++) {
        const int r = m0 + mi * 16 + (lane >> 2);
        const int c = n0 + 2 * (lane & 3);
#pragma unroll
        for (int nt = 0; nt < 8; nt++) {
            *(float2*)(Csm + r * CPAD + c + nt * 8) =
                make_float2(acc[mi][nt][0], acc[mi][nt][1]);
            *(float2*)(Csm + (r + 8) * CPAD + c + nt * 8) =
                make_float2(acc[mi][nt][2], acc[mi][nt][3]);
        }
    }
    __syncthreads();

    // Per-token epilogue: 2 threads per row, 64 cols each.
    {
        const int m = tid >> 1, half = tid & 1;
        const int t = t0 + m;
        const float* crow = Csm + m * CPAD + half * 64;
        float* orow = out + ((size_t)(b * NT + t) * NJ + j) * ND;
        float p = 0.0f;
#pragma unroll
        for (int cq = 0; cq < 16; cq++) {
            float4 v = *(const float4*)(crow + 4 * cq);
            float4 bb = __ldg((const float4*)(b_out + half * 64 + 4 * cq));
            float y0 = v.x + bb.x, y1 = v.y + bb.y, y2 = v.z + bb.z, y3 = v.w + bb.w;
            p = fmaf(y0, y0, p); p = fmaf(y1, y1, p);
            p = fmaf(y2, y2, p); p = fmaf(y3, y3, p);
            float* od = orow + 1 + half * 64 + 4 * cq;
            od[0] = y0; od[1] = y1; od[2] = y2; od[3] = y3;
        }
        p += __shfl_xor_sync(0xffffffffu, p, 1);
        if (half == 0) orow[0] = sqrtf(1.0f + p);
    }
}

// ---------------------------------------------------------------------------
extern "C" void kernel_launch(void* const* d_in, const int* in_sizes, int n_in,
                              void* d_out, int out_size) {
    (void)in_sizes; (void)n_in; (void)out_size;
    const float* x     = (const float*)d_in[0];
    const float* w_qkv = (const float*)d_in[1];
    const float* b_qkv = (const float*)d_in[2];
    const float* w_out = (const float*)d_in[3];
    const float* b_out = (const float*)d_in[4];
    float* out = (float*)d_out;

    cudaFuncSetAttribute(qkv_kernel, cudaFuncAttributeMaxDynamicSharedMemorySize, SMEM_K1);
    cudaFuncSetAttribute(out_kernel, cudaFuncAttributeMaxDynamicSharedMemorySize, SMEM_K3);

    qkv_kernel<<<NTOK / 128, 256, SMEM_K1>>>(x, w_qkv, b_qkv);
    kv_kernel<<<NBJ * NH, 256>>>();
    out_kernel<<<NTOK / 128, 256, SMEM_K3>>>(w_out, b_out, out);
}

// round 16
// speedup vs baseline: 1.9968x; 1.2905x over previous
#include <cuda_runtime.h>
#include <cuda_bf16.h>
#include <math.h>
#include <stdint.h>

// Problem constants
#define NB   8
#define NT   2048
#define NJ   17
#define ND   129
#define NH   8
#define DH   16
#define NBJ  (NB * NJ)        // 136
#define NTOK (NBJ * NT)       // 278528
#define QKVN 384
#define KVSZ 272              // 16x16 kv + 16 ksum per (bj,h)

// Scratch (device globals: allocation-free rule)
__device__ float g_qkvm[(size_t)NTOK * QKVN];          // phi(q), phi(k), v per token
__device__ float g_kvtab[(size_t)NBJ * NH * KVSZ];     // per (bj,h): kv[16][16], ksum[16]
// Pre-converted bf16 hi/lo weights (row-major [n][k], 256B rows)
__device__ __nv_bfloat16 g_wq_hi[3 * 128 * 128], g_wq_lo[3 * 128 * 128];
__device__ __nv_bfloat16 g_wo_hi[128 * 128],     g_wo_lo[128 * 128];

// ---------------- smem layout (dynamic) ----------------
// bf16 tiles, row stride 272B (136 bf16): ldmatrix conflict-free
// (272 mod 128 = 16 -> 8 rows hit 8 distinct 16B banks).
#define RSB      272
#define OFF_AHI  0
#define OFF_ALO  (128 * RSB)            // 34816
#define OFF_BHI  (2 * 128 * RSB)        // 69632  (B: 64 rows)
#define OFF_BLO  (OFF_BHI + 64 * RSB)   // 87040
#define SMEM_K1  (OFF_BLO + 64 * RSB)   // 104448
#define OFF_KV   SMEM_K1
#define SMEM_K3  (SMEM_K1 + NH * KVSZ * 4)  // 113152
#define CPAD     132                    // fp32 staging row stride (floats), K3

// ---------------------------- PTX helpers ----------------------------------
__device__ __forceinline__ uint32_t smem_u32(const void* p) {
    uint32_t a;
    asm("{ .reg .u64 t; cvta.to.shared.u64 t, %1; cvt.u32.u64 %0, t; }" : "=r"(a) : "l"(p));
    return a;
}

#define LDSM_X4(r0, r1, r2, r3, addr) \
    asm volatile("ldmatrix.sync.aligned.m8n8.x4.shared.b16 {%0,%1,%2,%3}, [%4];" \
                 : "=r"(r0), "=r"(r1), "=r"(r2), "=r"(r3) : "r"(addr))

#define MMA16816(d, a, b) \
    asm volatile("mma.sync.aligned.m16n8k16.row.col.f32.bf16.bf16.f32 " \
                 "{%0,%1,%2,%3}, {%4,%5,%6,%7}, {%8,%9}, {%0,%1,%2,%3};" \
                 : "+f"((d)[0]), "+f"((d)[1]), "+f"((d)[2]), "+f"((d)[3]) \
                 : "r"((a)[0]), "r"((a)[1]), "r"((a)[2]), "r"((a)[3]), \
                   "r"((b)[0]), "r"((b)[1]))

__device__ __forceinline__ void cvt_hilo(float v, __nv_bfloat16& h, __nv_bfloat16& l) {
    h = __float2bfloat16(v);
    l = __float2bfloat16(v - __bfloat162float(h));
}

// Copy a 64x128 bf16 hi/lo pair (row-major, 256B rows) into the B smem tiles.
__device__ __forceinline__ void copy_b(char* smc, const __nv_bfloat16* __restrict__ hi,
                                       const __nv_bfloat16* __restrict__ lo, int tid) {
#pragma unroll
    for (int it = 0; it < 4; it++) {
        int idx = tid + it * 256;           // 0..1023
        int r = idx >> 4, c = idx & 15;
        *(uint4*)(smc + OFF_BHI + r * RSB + c * 16) =
            __ldg((const uint4*)(hi + r * 128) + c);
        *(uint4*)(smc + OFF_BLO + r * RSB + c * 16) =
            __ldg((const uint4*)(lo + r * 128) + c);
    }
}

// 3-term bf16-split GEMM, warp tile M=32 x N=32, K=128, k-outer fragment
// sharing: 8 LDSM.x4 + 24 MMA per k-step.
__device__ __forceinline__ void mma_split32(uint32_t aA_hi, uint32_t aA_lo,
                                            uint32_t aB_hi, uint32_t aB_lo,
                                            float acc[2][4][4]) {
#pragma unroll 4
    for (int ks = 0; ks < 8; ks++) {
        const uint32_t ko = (uint32_t)ks * 32;
        uint32_t ah[2][4], al[2][4];
#pragma unroll
        for (int mi = 0; mi < 2; mi++) {
            LDSM_X4(ah[mi][0], ah[mi][1], ah[mi][2], ah[mi][3],
                    aA_hi + (uint32_t)mi * (16 * RSB) + ko);
            LDSM_X4(al[mi][0], al[mi][1], al[mi][2], al[mi][3],
                    aA_lo + (uint32_t)mi * (16 * RSB) + ko);
        }
        uint32_t bh[4][2], bl[4][2];
#pragma unroll
        for (int nb = 0; nb < 2; nb++) {
            uint32_t t0, t1, t2, t3;
            LDSM_X4(t0, t1, t2, t3, aB_hi + (uint32_t)nb * (16 * RSB) + ko);
            bh[2 * nb][0] = t0; bh[2 * nb][1] = t1;
            bh[2 * nb + 1][0] = t2; bh[2 * nb + 1][1] = t3;
            LDSM_X4(t0, t1, t2, t3, aB_lo + (uint32_t)nb * (16 * RSB) + ko);
            bl[2 * nb][0] = t0; bl[2 * nb][1] = t1;
            bl[2 * nb + 1][0] = t2; bl[2 * nb + 1][1] = t3;
        }
#pragma unroll
        for (int mi = 0; mi < 2; mi++)
#pragma unroll
            for (int nt = 0; nt < 4; nt++) {
                MMA16816(acc[mi][nt], ah[mi], bh[nt]);
                MMA16816(acc[mi][nt], al[mi], bh[nt]);
                MMA16816(acc[mi][nt], ah[mi], bl[nt]);
            }
    }
}

// ---------------------------------------------------------------------------
// Kernel 0: one-shot weight conversion fp32 -> bf16 hi/lo.
// ---------------------------------------------------------------------------
__global__ void __launch_bounds__(256)
wconv_kernel(const float* __restrict__ wq, const float* __restrict__ wo) {
    int i = blockIdx.x * 256 + threadIdx.x;
    if (i < 3 * 128 * 128) {
        __nv_bfloat16 h, l;
        cvt_hilo(__ldg(wq + i), h, l);
        g_wq_hi[i] = h; g_wq_lo[i] = l;
    }
    if (i < 128 * 128) {
        __nv_bfloat16 h, l;
        cvt_hilo(__ldg(wo + i), h, l);
        g_wo_hi[i] = h; g_wo_lo[i] = l;
    }
}

// ---------------------------------------------------------------------------
// Kernel 1: qkv GEMM via HMMA. One CTA = 128 tokens; loops 6 (slab, N-half)
// steps against pre-converted weights. 2 CTAs/SM.
// ---------------------------------------------------------------------------
__global__ void __launch_bounds__(256, 2)
qkv_kernel(const float* __restrict__ x, const float* __restrict__ b_qkv) {
    extern __shared__ char smc[];
    const uint32_t sb = smem_u32(smc);
    const int tid = threadIdx.x, lane = tid & 31, wp = tid >> 5;

    const int tok0 = blockIdx.x * 128;
    const int bj = tok0 / NT;
    const int t0 = tok0 - bj * NT;
    const int b = bj / NJ, j = bj - b * NJ;
    const float* xbase = x + ((size_t)(b * NT + t0) * NJ + j) * ND + 1;  // skip time col
    const size_t xstride = (size_t)NJ * ND;

    // A tile: 128 tokens x 128 dims -> hi/lo bf16 (x rows 4B-aligned: scalar ld)
    for (int r = wp; r < 128; r += 8) {
        const float* xr = xbase + (size_t)r * xstride;
#pragma unroll
        for (int cb = 0; cb < 128; cb += 64) {
            int c = cb + 2 * lane;
            float v0 = __ldg(xr + c), v1 = __ldg(xr + c + 1);
            __nv_bfloat16 h0, l0, h1, l1;
            cvt_hilo(v0, h0, l0);
            cvt_hilo(v1, h1, l1);
            uint32_t off = (uint32_t)r * RSB + (uint32_t)c * 2;
            __nv_bfloat162 hp; hp.x = h0; hp.y = h1;
            __nv_bfloat162 lp; lp.x = l0; lp.y = l1;
            *(__nv_bfloat162*)(smc + OFF_AHI + off) = hp;
            *(__nv_bfloat162*)(smc + OFF_ALO + off) = lp;
        }
    }

    // Warp tiling (4x2 of 32x32) + per-lane ldmatrix offsets
    const int wm = wp & 3, wn = wp >> 2;
    const int m0 = wm * 32, n0 = wn * 32;
    const uint32_t a_loff = (uint32_t)(lane & 7) * RSB + (uint32_t)((lane >> 3) & 1) * (8 * RSB)
                          + (uint32_t)(lane >> 4) * 16;
    const uint32_t b_loff = (uint32_t)(lane & 7) * RSB + (uint32_t)((lane >> 3) & 1) * 16
                          + (uint32_t)(lane >> 4) * (8 * RSB);
    const uint32_t aA_hi = sb + OFF_AHI + (uint32_t)m0 * RSB + a_loff;
    const uint32_t aA_lo = sb + OFF_ALO + (uint32_t)m0 * RSB + a_loff;
    const uint32_t aB_hi = sb + OFF_BHI + (uint32_t)n0 * RSB + b_loff;
    const uint32_t aB_lo = sb + OFF_BLO + (uint32_t)n0 * RSB + b_loff;

    for (int sh = 0; sh < 6; sh++) {
        const int s = sh >> 1, half = sh & 1;
        if (sh) __syncthreads();  // all warps past previous MMA before B overwrite
        copy_b(smc, g_wq_hi + (size_t)(s * 128 + half * 64) * 128,
                    g_wq_lo + (size_t)(s * 128 + half * 64) * 128, tid);
        __syncthreads();          // A (first iter) + B ready

        float acc[2][4][4];
#pragma unroll
        for (int mi = 0; mi < 2; mi++)
#pragma unroll
            for (int nt = 0; nt < 4; nt++)
#pragma unroll
                for (int u = 0; u < 4; u++) acc[mi][nt][u] = 0.0f;

        mma_split32(aA_hi, aA_lo, aB_hi, aB_lo, acc);

        // Fragment-direct epilogue: +bias, phi for q/k slabs, store to scratch.
        const int cb = s * 128 + half * 64;
        float2 bv[4];
#pragma unroll
        for (int nt = 0; nt < 4; nt++)
            bv[nt] = __ldg((const float2*)(b_qkv + cb + n0 + nt * 8 + 2 * (lane & 3)));

#pragma unroll
        for (int mi = 0; mi < 2; mi++) {
            const int r0 = m0 + mi * 16 + (lane >> 2);
            float* row0 = g_qkvm + (size_t)(tok0 + r0) * QKVN + cb + n0 + 2 * (lane & 3);
            float* row1 = row0 + 8 * QKVN;
#pragma unroll
            for (int nt = 0; nt < 4; nt++) {
                float y00 = acc[mi][nt][0] + bv[nt].x;
                float y01 = acc[mi][nt][1] + bv[nt].y;
                float y10 = acc[mi][nt][2] + bv[nt].x;
                float y11 = acc[mi][nt][3] + bv[nt].y;
                if (s < 2) {  // phi = elu + 1
                    y00 = (y00 > 0.0f) ? (y00 + 1.0f) : expf(y00);
                    y01 = (y01 > 0.0f) ? (y01 + 1.0f) : expf(y01);
                    y10 = (y10 > 0.0f) ? (y10 + 1.0f) : expf(y10);
                    y11 = (y11 > 0.0f) ? (y11 + 1.0f) : expf(y11);
                }
                *(float2*)(row0 + nt * 8) = make_float2(y00, y01);
                *(float2*)(row1 + nt * 8) = make_float2(y10, y11);
            }
        }
    }
}

// ---------------------------------------------------------------------------
// Kernel 2: per (bj, h): kv[d][e] = sum_t k_m[t,d]*v[t,e], ksum[d] = sum_t k_m[t,d]
// ---------------------------------------------------------------------------
__global__ void __launch_bounds__(256, 4)
kv_kernel() {
    const int bh = blockIdx.x;
    const int bj = bh >> 3, h = bh & 7;
    const int tid = threadIdx.x;
    const int i = tid >> 4, e = tid & 15;
    __shared__ float ks[16][16];
    __shared__ float vs[16][16];
    float kv = 0.0f, ksm = 0.0f;
    const size_t base = (size_t)bj * NT * QKVN + 128 + h * DH;  // k_m slab offset
    for (int tb = 0; tb < NT; tb += 16) {
#pragma unroll
        for (int r = 0; r < 2; r++) {
            int idx = tid + r * 256;
            int tt = idx >> 5;
            int which = (idx >> 4) & 1;  // 0 -> k_m, 1 -> v (offset +128)
            int li = idx & 15;
            float val = g_qkvm[base + (size_t)(tb + tt) * QKVN + which * 128 + li];
            if (which == 0) ks[tt][li] = val; else vs[tt][li] = val;
        }
        __syncthreads();
#pragma unroll
        for (int tt = 0; tt < 16; tt++) {
            float kk = ks[tt][i];
            kv = fmaf(kk, vs[tt][e], kv);
            if (e == 0) ksm += kk;
        }
        __syncthreads();
    }
    float* dst = g_kvtab + (size_t)bh * KVSZ;
    dst[i * 16 + e] = kv;
    if (e == 0) dst[256 + i] = ksm;
}

// ---------------------------------------------------------------------------
// Kernel 3: agg = (q_m @ kv) / clip(q_m . ksum, EPS) -> bf16 hi/lo A tile,
// y = agg @ w_out^T + b via HMMA (two N-halves, accs in regs), y_time epilogue.
// ---------------------------------------------------------------------------
__global__ void __launch_bounds__(256, 2)
out_kernel(const float* __restrict__ b_out, float* __restrict__ out) {
    extern __shared__ char smc[];
    const uint32_t sb = smem_u32(smc);
    float* skv = (float*)(smc + OFF_KV);
    const int tid = threadIdx.x, lane = tid & 31, wp = tid >> 5;

    const int tok0 = blockIdx.x * 128;
    const int bj = tok0 / NT;
    const int t0 = tok0 - bj * NT;
    const int b = bj / NJ, j = bj - b * NJ;

    for (int idx = tid; idx < NH * KVSZ; idx += 256)
        skv[idx] = g_kvtab[(size_t)bj * NH * KVSZ + idx];
    __syncthreads();

    // Phase 1: agg_flat for 128 tokens (2 threads/token, 4 heads each),
    // written as bf16 hi/lo directly into the A tile.
    {
        const int m  = tid >> 1;
        const int hb = (tid & 1) * 4;
        const float* qrow = g_qkvm + (size_t)(tok0 + m) * QKVN;  // q_m at slab 0
#pragma unroll
        for (int hh = 0; hh < 4; hh++) {
            const int h = hb + hh;
            float q[16];
            const float4* q4 = (const float4*)(qrow + h * DH);
#pragma unroll
            for (int u = 0; u < 4; u++) {
                float4 t = q4[u];
                q[4 * u] = t.x; q[4 * u + 1] = t.y; q[4 * u + 2] = t.z; q[4 * u + 3] = t.w;
            }
            const float* kvh = skv + h * KVSZ;
            float a[16];
#pragma unroll
            for (int e2 = 0; e2 < 16; e2++) a[e2] = 0.0f;
            float denom = 0.0f;
#pragma unroll
            for (int i = 0; i < 16; i++) {
                const float qi = q[i];
                const float4* kr = (const float4*)(kvh + i * 16);
#pragma unroll
                for (int u = 0; u < 4; u++) {
                    float4 t = kr[u];
                    a[4 * u]     = fmaf(qi, t.x, a[4 * u]);
                    a[4 * u + 1] = fmaf(qi, t.y, a[4 * u + 1]);
                    a[4 * u + 2] = fmaf(qi, t.z, a[4 * u + 2]);
                    a[4 * u + 3] = fmaf(qi, t.w, a[4 * u + 3]);
                }
                denom = fmaf(qi, kvh[256 + i], denom);
            }
            denom = fmaxf(denom, 1e-6f);
            const float inv = 1.0f / denom;
#pragma unroll
            for (int e2 = 0; e2 < 16; e2 += 2) {
                __nv_bfloat16 h0, l0, h1, l1;
                cvt_hilo(a[e2] * inv, h0, l0);
                cvt_hilo(a[e2 + 1] * inv, h1, l1);
                uint32_t off = (uint32_t)m * RSB + (uint32_t)(h * DH + e2) * 2;
                __nv_bfloat162 hp; hp.x = h0; hp.y = h1;
                __nv_bfloat162 lp; lp.x = l0; lp.y = l1;
                *(__nv_bfloat162*)(smc + OFF_AHI + off) = hp;
                *(__nv_bfloat162*)(smc + OFF_ALO + off) = lp;
            }
        }
    }
    copy_b(smc, g_wo_hi, g_wo_lo, tid);  // N-half 0, independent of A writes
    __syncthreads();

    const int wm = wp & 3, wn = wp >> 2;
    const int m0 = wm * 32, n0 = wn * 32;
    const uint32_t a_loff = (uint32_t)(lane & 7) * RSB + (uint32_t)((lane >> 3) & 1) * (8 * RSB)
                          + (uint32_t)(lane >> 4) * 16;
    const uint32_t b_loff = (uint32_t)(lane & 7) * RSB + (uint32_t)((lane >> 3) & 1) * 16
                          + (uint32_t)(lane >> 4) * (8 * RSB);
    const uint32_t aA_hi = sb + OFF_AHI + (uint32_t)m0 * RSB + a_loff;
    const uint32_t aA_lo = sb + OFF_ALO + (uint32_t)m0 * RSB + a_loff;
    const uint32_t aB_hi = sb + OFF_BHI + (uint32_t)n0 * RSB + b_loff;
    const uint32_t aB_lo = sb + OFF_BLO + (uint32_t)n0 * RSB + b_loff;

    float acc0[2][4][4], acc1[2][4][4];
#pragma unroll
    for (int mi = 0; mi < 2; mi++)
#pragma unroll
        for (int nt = 0; nt < 4; nt++)
#pragma unroll
            for (int u = 0; u < 4; u++) { acc0[mi][nt][u] = 0.0f; acc1[mi][nt][u] = 0.0f; }

    mma_split32(aA_hi, aA_lo, aB_hi, aB_lo, acc0);
    __syncthreads();
    copy_b(smc, g_wo_hi + 64 * 128, g_wo_lo + 64 * 128, tid);  // N-half 1
    __syncthreads();
    mma_split32(aA_hi, aA_lo, aB_hi, aB_lo, acc1);
    __syncthreads();  // A no longer needed -> stage over it

    float* Csm = (float*)(smc + OFF_AHI);  // 128 x CPAD floats (67584B <= 69632B)
#pragma unroll
    for (int mi = 0; mi < 2; mi++) {
        const int r = m0 + mi * 16 + (lane >> 2);
        const int c = n0 + 2 * (lane & 3);
#pragma unroll
        for (int nt = 0; nt < 4; nt++) {
            *(float2*)(Csm + r * CPAD + c + nt * 8) =
                make_float2(acc0[mi][nt][0], acc0[mi][nt][1]);
            *(float2*)(Csm + (r + 8) * CPAD + c + nt * 8) =
                make_float2(acc0[mi][nt][2], acc0[mi][nt][3]);
            *(float2*)(Csm + r * CPAD + 64 + c + nt * 8) =
                make_float2(acc1[mi][nt][0], acc1[mi][nt][1]);
            *(float2*)(Csm + (r + 8) * CPAD + 64 + c + nt * 8) =
                make_float2(acc1[mi][nt][2], acc1[mi][nt][3]);
        }
    }
    __syncthreads();

    // Per-token epilogue: 2 threads per row, 64 cols each.
    {
        const int m = tid >> 1, half = tid & 1;
        const int t = t0 + m;
        const float* crow = Csm + m * CPAD + half * 64;
        float* orow = out + ((size_t)(b * NT + t) * NJ + j) * ND;
        float p = 0.0f;
#pragma unroll
        for (int cq = 0; cq < 16; cq++) {
            float4 v = *(const float4*)(crow + 4 * cq);
            float4 bb = __ldg((const float4*)(b_out + half * 64 + 4 * cq));
            float y0 = v.x + bb.x, y1 = v.y + bb.y, y2 = v.z + bb.z, y3 = v.w + bb.w;
            p = fmaf(y0, y0, p); p = fmaf(y1, y1, p);
            p = fmaf(y2, y2, p); p = fmaf(y3, y3, p);
            float* od = orow + 1 + half * 64 + 4 * cq;
            od[0] = y0; od[1] = y1; od[2] = y2; od[3] = y3;
        }
        p += __shfl_xor_sync(0xffffffffu, p, 1);
        if (half == 0) orow[0] = sqrtf(1.0f + p);
    }
}

// ---------------------------------------------------------------------------
extern "C" void kernel_launch(void* const* d_in, const int* in_sizes, int n_in,
                              void* d_out, int out_size) {
    (void)in_sizes; (void)n_in; (void)out_size;
    const float* x     = (const float*)d_in[0];
    const float* w_qkv = (const float*)d_in[1];
    const float* b_qkv = (const float*)d_in[2];
    const float* w_out = (const float*)d_in[3];
    const float* b_out = (const float*)d_in[4];
    float* out = (float*)d_out;

    cudaFuncSetAttribute(qkv_kernel, cudaFuncAttributeMaxDynamicSharedMemorySize, SMEM_K1);
    cudaFuncSetAttribute(out_kernel, cudaFuncAttributeMaxDynamicSharedMemorySize, SMEM_K3);

    wconv_kernel<<<192, 256>>>(w_qkv, w_out);
    qkv_kernel<<<NTOK / 128, 256, SMEM_K1>>>(x, b_qkv);
    kv_kernel<<<NBJ * NH, 256>>>();
    out_kernel<<<NTOK / 128, 256, SMEM_K3>>>(b_out, out);
}